// round 4
// baseline (speedup 1.0000x reference)
#include <cuda_runtime.h>

typedef unsigned long long ull;

#define HH 512
#define WW 512
#define TW 128   // tile cols
#define TH 16    // tile rows
#define XW 132   // padded shared row width in words (528B, 16B-aligned stride)

__device__ __forceinline__ ull pk(float lo, float hi) {
    ull r;
    asm("mov.b64 %0, {%1,%2};" : "=l"(r) : "f"(lo), "f"(hi));
    return r;
}
__device__ __forceinline__ ull ffma2(ull a, ull b, ull c) {
    ull d;
    asm("fma.rn.f32x2 %0, %1, %2, %3;" : "=l"(d) : "l"(a), "l"(b), "l"(c));
    return d;
}
__device__ __forceinline__ ull fadd2(ull a, ull b) {
    ull d;
    asm("add.rn.f32x2 %0, %1, %2;" : "=l"(d) : "l"(a), "l"(b));
    return d;
}
// (a.hi, b.lo) as a 64-bit pair — compiles to 2 MOV32
__device__ __forceinline__ ull cross(ull a, ull b) {
    ull r;
    asm("{\n\t"
        ".reg .b32 al, ah, bl, bh;\n\t"
        "mov.b64 {al, ah}, %1;\n\t"
        "mov.b64 {bl, bh}, %2;\n\t"
        "mov.b64 %0, {ah, bl};\n\t"
        "}" : "=l"(r) : "l"(a), "l"(b));
    return r;
}

// Main kernel: warp = 1 channel (2 sequential passes), 4 px/thread, 128x16 tile.
// Computes interior formula everywhere (base includes full extra-sum S);
// image-border pixels get corrected by fixup_border afterwards.
__global__ void __launch_bounds__(256, 1) conv_main(
    const float* __restrict__ x,   // [8,3,512,512]
    const float* __restrict__ ei,  // [8,192]
    const float* __restrict__ wm,  // [64,3,3,3]
    const float* __restrict__ bm,  // [64]
    const float* __restrict__ we,  // [64,3,3,3]
    const float* __restrict__ be,  // [64]
    float* __restrict__ out)       // [8,64,512,512]
{
    __shared__ __align__(16) float xs[3][TH + 2][XW];

    const int tid = threadIdx.x;
    const int w0 = blockIdx.x * TW, h0 = blockIdx.y * TH;
    const int b = blockIdx.z >> 2, cg = blockIdx.z & 3;

    // stage x patch: rows h0-1..h0+TH, cols w0-1..w0+TW+1; word = localcol+1 shift
    for (int i = tid; i < 3 * (TH + 2) * 131; i += 256) {
        int ci = i / 2358;                 // 2358 = 18*131
        int rem = i - ci * 2358;
        int r = rem / 131, col = rem - r * 131;
        int gh = h0 - 1 + r, gw = w0 - 1 + col;
        float v = 0.f;
        if ((unsigned)gh < HH && (unsigned)gw < WW)
            v = x[((b * 3 + ci) * HH + gh) * WW + gw];
        xs[ci][r][col] = v;
    }
    __syncthreads();

    const int lane = tid & 31, wid = tid >> 5;
    const int colw = lane * 4;   // word index of x[p-1]; pixel p = 4*lane (local)

    #pragma unroll 1
    for (int pass = 0; pass < 2; pass++) {
        const int c = cg * 16 + pass * 8 + wid;

        // channel weights -> registers as (w,w) pairs (uniform LDG, once per pass)
        ull wp[27];
        #pragma unroll
        for (int t = 0; t < 27; t++) {
            float w = __ldg(wm + c * 27 + t);
            wp[t] = pk(w, w);
        }
        // base = b_main + b_extra + full extra sum S (interior-correct everywhere)
        float S = 0.f;
        #pragma unroll
        for (int e = 0; e < 3; e++) {
            float s9 = 0.f;
            #pragma unroll
            for (int t = 0; t < 9; t++) s9 += __ldg(we + (c * 3 + e) * 9 + t);
            S += __ldg(ei + b * 192 + c * 3 + e) * s9;
        }
        float basef = __ldg(bm + c) + __ldg(be + c) + S;
        const ull base = pk(basef, basef);

        float* outp = out + (((size_t)(b * 64 + c)) * HH + h0) * WW + w0 + colw;

        #pragma unroll 1
        for (int r0 = 0; r0 < TH; r0 += 4) {
            #pragma unroll
            for (int rr = 0; rr < 4; rr++) {
                const int r = r0 + rr;
                ull A0 = base, A1 = 0ULL, B0 = base, B1 = 0ULL;
                #pragma unroll
                for (int ci = 0; ci < 3; ci++) {
                    #pragma unroll
                    for (int dy = 0; dy < 3; dy++) {
                        const float* p = &xs[ci][r + dy][colw];
                        ulonglong2 q = *reinterpret_cast<const ulonglong2*>(p);
                        ull e2 = *reinterpret_cast<const ull*>(p + 4);
                        const int t = ci * 9 + dy * 3;
                        // q.x=(x[p-1],x[p])  q.y=(x[p+1],x[p+2])  e2=(x[p+3],x[p+4])
                        A0 = ffma2(wp[t],     q.x,             A0);  // kx=0, pix(0,1)
                        B0 = ffma2(wp[t],     q.y,             B0);  // kx=0, pix(2,3)
                        A1 = ffma2(wp[t + 1], cross(q.x, q.y), A1);  // kx=1, pix(0,1)
                        B1 = ffma2(wp[t + 1], cross(q.y, e2),  B1);  // kx=1, pix(2,3)
                        A0 = ffma2(wp[t + 2], q.y,             A0);  // kx=2, pix(0,1)
                        B0 = ffma2(wp[t + 2], e2,              B0);  // kx=2, pix(2,3)
                    }
                }
                ulonglong2 res;
                res.x = fadd2(A0, A1);
                res.y = fadd2(B0, B1);
                *reinterpret_cast<ulonglong2*>(outp + (size_t)r * WW) = res;
            }
        }
    }
}

// Border fixup: adds the extra-term border corrections (kernel taps falling
// outside the image were included in S; subtract them on the border frame).
__global__ void fixup_border(
    const float* __restrict__ ei,  // [8,192]
    const float* __restrict__ we,  // [64,3,3,3]
    float* __restrict__ out)       // [8,64,512,512]
{
    const int b = blockIdx.x >> 6, c = blockIdx.x & 63;
    const int t = threadIdx.x;     // 0..511

    float rT = 0, rB = 0, kL = 0, kR = 0;
    float tTL = 0, tTR = 0, tBL = 0, tBR = 0;
    #pragma unroll
    for (int e = 0; e < 3; e++) {
        float v = ei[b * 192 + c * 3 + e];
        const float* wp = we + (c * 3 + e) * 9;
        #pragma unroll
        for (int ky = 0; ky < 3; ky++) {
            #pragma unroll
            for (int kx = 0; kx < 3; kx++) {
                float q = v * wp[ky * 3 + kx];
                if (ky == 0) rT += q;
                if (ky == 2) rB += q;
                if (kx == 0) kL += q;
                if (kx == 2) kR += q;
                if (ky == 0 && kx == 0) tTL += q;
                if (ky == 0 && kx == 2) tTR += q;
                if (ky == 2 && kx == 0) tBL += q;
                if (ky == 2 && kx == 2) tBR += q;
            }
        }
    }
    float ml = (t == 0) ? 1.f : 0.f;
    float mr = (t == WW - 1) ? 1.f : 0.f;
    float* img = out + ((size_t)(b * 64 + c)) * HH * WW;
    // top & bottom rows (include corners)
    img[t] += -rT + ml * (-kL + tTL) + mr * (-kR + tTR);
    img[(size_t)(HH - 1) * WW + t] += -rB + ml * (-kL + tBL) + mr * (-kR + tBR);
    // left & right columns (exclude corners)
    if (t >= 1 && t <= HH - 2) {
        img[(size_t)t * WW] += -kL;
        img[(size_t)t * WW + WW - 1] += -kR;
    }
}

extern "C" void kernel_launch(void* const* d_in, const int* in_sizes, int n_in,
                              void* d_out, int out_size)
{
    const float* x  = (const float*)d_in[0];
    const float* ei = (const float*)d_in[1];
    const float* wm = (const float*)d_in[2];
    const float* bm = (const float*)d_in[3];
    const float* we = (const float*)d_in[4];
    const float* be = (const float*)d_in[5];
    float* out = (float*)d_out;

    dim3 grid(WW / TW, HH / TH, 32);   // 4 x 32 x 32 = 4096 CTAs
    conv_main<<<grid, 256>>>(x, ei, wm, bm, we, be, out);
    fixup_border<<<512, 512>>>(ei, we, out);
}